// round 1
// baseline (speedup 1.0000x reference)
#include <cuda_runtime.h>

#define BB 16
#define TT 2048
#define FF 512

// Scratch (allocation-free rule: device globals)
__device__ float g_wt[BB * TT];      // gate weights
__device__ int   g_vlist[BB * TT];   // packed valley positions per batch
__device__ int   g_nv[BB];           // number of valleys k per batch
__device__ int   g_newlen[BB];       // new_lengths per batch

// ---------------------------------------------------------------------------
// Kernel 1: wt[b,t] = sigmoid(dot(x[b,t,:], w) + bias). One warp per row.
// ---------------------------------------------------------------------------
__global__ void k_gate(const float* __restrict__ x,
                       const float* __restrict__ w,
                       const float* __restrict__ bias) {
    int row  = blockIdx.x * 8 + (threadIdx.x >> 5);   // 8 warps / block
    int lane = threadIdx.x & 31;
    if (row >= BB * TT) return;

    const float4* xr = (const float4*)(x + (size_t)row * FF);
    const float4* wr = (const float4*)w;

    float s = 0.f;
#pragma unroll
    for (int j = lane; j < FF / 4; j += 32) {
        float4 a = xr[j];
        float4 c = wr[j];
        s += a.x * c.x + a.y * c.y + a.z * c.z + a.w * c.w;
    }
#pragma unroll
    for (int o = 16; o; o >>= 1) s += __shfl_down_sync(0xffffffffu, s, o);

    if (lane == 0) {
        float z = s + bias[0];
        g_wt[row] = 1.f / (1.f + expf(-z));
    }
}

// ---------------------------------------------------------------------------
// Kernel 2: per batch, find strict local minima of wt and left-pack their
// positions. valley[0] and valley[T-1] are always false (sigmoid > 0 and
// zero-padding in the reference), handled by the 0-padding below.
// ---------------------------------------------------------------------------
__global__ void k_valleys() {
    __shared__ float sw[TT];
    __shared__ int   scnt[256];

    int b   = blockIdx.x;
    int tid = threadIdx.x;                 // 256 threads

    for (int t = tid; t < TT; t += 256) sw[t] = g_wt[b * TT + t];
    __syncthreads();

    const int PER = TT / 256;              // 8 consecutive t per thread
    int base = tid * PER;
    unsigned char fl[PER];
    int c = 0;
#pragma unroll
    for (int j = 0; j < PER; j++) {
        int   t   = base + j;
        float wtt = sw[t];
        float bef = (t == 0)      ? 0.f : sw[t - 1];
        float aft = (t == TT - 1) ? 0.f : sw[t + 1];
        bool  v   = (wtt < bef) && (wtt < aft);
        fl[j] = v ? 1 : 0;
        c += v ? 1 : 0;
    }
    scnt[tid] = c;
    __syncthreads();

    // inclusive scan over 256 per-thread counts
    for (int off = 1; off < 256; off <<= 1) {
        int v = (tid >= off) ? scnt[tid - off] : 0;
        __syncthreads();
        scnt[tid] += v;
        __syncthreads();
    }

    int pos = scnt[tid] - c;               // exclusive prefix
#pragma unroll
    for (int j = 0; j < PER; j++) {
        if (fl[j]) g_vlist[b * TT + (pos++)] = base + j;
    }
    if (tid == 255) g_nv[b] = scnt[255];
}

// ---------------------------------------------------------------------------
// Kernel 3: new_lengths[b] = int( min(seq,T)/min(seq0,T) * max_counts )
// where counts[b] = nv[b] + 1 (segments = valleys + 1).
// ---------------------------------------------------------------------------
__global__ void k_newlen(const int* __restrict__ seq_len) {
    int tid = threadIdx.x;
    __shared__ int mc;
    if (tid == 0) {
        int m = 0;
        for (int b = 0; b < BB; b++) {
            int c = g_nv[b] + 1;
            if (c > m) m = c;
        }
        mc = m;
    }
    __syncthreads();
    if (tid < BB) {
        int len  = min(seq_len[tid], TT);
        int len0 = min(seq_len[0], TT);
        float r  = (float)len / (float)len0 * (float)mc;
        g_newlen[tid] = (int)r;            // trunc toward zero (values >= 0)
    }
}

// ---------------------------------------------------------------------------
// Kernel 4: pooled[b,i,:] = segsum(wt*x) / max(segsum(wt), 1e-6); rows i >=
// counts are exact zeros (matches reference: num=0, den clipped to 1e-6).
// Optionally writes new_mask (as output dtype 0/1) after pooled.
// Segment i: start = (i==0)?0:v[i-1], end = (i<k)? min(v[i]+2,T) : T.
// One block per (segment row, batch); 128 threads * float4 = 512 features.
// ---------------------------------------------------------------------------
__global__ void k_pool(const float* __restrict__ x,
                       float* __restrict__ out,
                       int write_mask) {
    int i   = blockIdx.x;
    int b   = blockIdx.y;
    int tid = threadIdx.x;                 // 128

    float* orow = out + ((size_t)b * TT + i) * FF;
    int k = g_nv[b];
    int n = k + 1;

    if (i >= n) {
        float4 z = make_float4(0.f, 0.f, 0.f, 0.f);
        ((float4*)orow)[tid] = z;
    } else {
        int s = (i == 0) ? 0 : g_vlist[b * TT + i - 1];
        int e = (i < k) ? min(g_vlist[b * TT + i] + 2, TT) : TT;

        const float* xb = x + (size_t)b * TT * FF;
        float4 acc = make_float4(0.f, 0.f, 0.f, 0.f);
        float  den = 0.f;
        for (int t = s; t < e; t++) {
            float  wv = g_wt[b * TT + t];
            den += wv;
            float4 xv = ((const float4*)(xb + (size_t)t * FF))[tid];
            acc.x += wv * xv.x;
            acc.y += wv * xv.y;
            acc.z += wv * xv.z;
            acc.w += wv * xv.w;
        }
        den = fmaxf(den, 1e-6f);
        acc.x /= den; acc.y /= den; acc.z /= den; acc.w /= den;
        ((float4*)orow)[tid] = acc;
    }

    if (write_mask && tid == 0) {
        float* m = out + (size_t)BB * TT * FF;
        m[(size_t)b * TT + i] = (i < g_newlen[b]) ? 1.f : 0.f;
    }
}

// ---------------------------------------------------------------------------
extern "C" void kernel_launch(void* const* d_in, const int* in_sizes, int n_in,
                              void* d_out, int out_size) {
    const float* x    = (const float*)d_in[0];   // [B,T,F] f32
    const float* w    = (const float*)d_in[1];   // [F,1]  f32
    const float* bias = (const float*)d_in[2];   // [1]    f32
    const int*   seq  = (const int*)d_in[3];     // [B]    i32
    float* out = (float*)d_out;

    int write_mask = (out_size >= BB * TT * FF + BB * TT) ? 1 : 0;

    k_gate<<<(BB * TT) / 8, 256>>>(x, w, bias);
    k_valleys<<<BB, 256>>>();
    k_newlen<<<1, 32>>>(seq);
    dim3 grid(TT, BB);
    k_pool<<<grid, 128>>>(x, out, write_mask);
}

// round 2
// speedup vs baseline: 1.0624x; 1.0624x over previous
#include <cuda_runtime.h>

#define BB 16
#define TT 2048
#define FF 512

// Scratch (allocation-free rule: device globals)
__device__ float g_wt[BB * TT];      // gate weights
__device__ int   g_vlist[BB * TT];   // packed valley positions per batch
__device__ int   g_nv[BB];           // number of valleys k per batch

// ---------------------------------------------------------------------------
// Kernel 1: wt[b,t] = sigmoid(dot(x[b,t,:], w) + bias). One warp per row.
// Normal (caching) loads: warms L2 with all of x (64 MB < 126 MB L2).
// ---------------------------------------------------------------------------
__global__ void k_gate(const float* __restrict__ x,
                       const float* __restrict__ w,
                       const float* __restrict__ bias) {
    int row  = blockIdx.x * 8 + (threadIdx.x >> 5);   // 8 warps / block
    int lane = threadIdx.x & 31;
    if (row >= BB * TT) return;

    const float4* xr = (const float4*)(x + (size_t)row * FF);
    const float4* wr = (const float4*)w;

    float s = 0.f;
#pragma unroll
    for (int j = lane; j < FF / 4; j += 32) {
        float4 a = xr[j];
        float4 c = wr[j];
        s += a.x * c.x + a.y * c.y + a.z * c.z + a.w * c.w;
    }
#pragma unroll
    for (int o = 16; o; o >>= 1) s += __shfl_down_sync(0xffffffffu, s, o);

    if (lane == 0) {
        float z = s + bias[0];
        g_wt[row] = 1.f / (1.f + expf(-z));
    }
}

// ---------------------------------------------------------------------------
// Kernel 2: per batch, find strict local minima of wt and left-pack positions.
// ---------------------------------------------------------------------------
__global__ void k_valleys() {
    __shared__ float sw[TT];
    __shared__ int   scnt[256];

    int b   = blockIdx.x;
    int tid = threadIdx.x;                 // 256 threads

    for (int t = tid; t < TT; t += 256) sw[t] = g_wt[b * TT + t];
    __syncthreads();

    const int PER = TT / 256;              // 8 consecutive t per thread
    int base = tid * PER;
    unsigned char fl[PER];
    int c = 0;
#pragma unroll
    for (int j = 0; j < PER; j++) {
        int   t   = base + j;
        float wtt = sw[t];
        float bef = (t == 0)      ? 0.f : sw[t - 1];
        float aft = (t == TT - 1) ? 0.f : sw[t + 1];
        bool  v   = (wtt < bef) && (wtt < aft);
        fl[j] = v ? 1 : 0;
        c += v ? 1 : 0;
    }
    scnt[tid] = c;
    __syncthreads();

    for (int off = 1; off < 256; off <<= 1) {
        int v = (tid >= off) ? scnt[tid - off] : 0;
        __syncthreads();
        scnt[tid] += v;
        __syncthreads();
    }

    int pos = scnt[tid] - c;               // exclusive prefix
#pragma unroll
    for (int j = 0; j < PER; j++) {
        if (fl[j]) g_vlist[b * TT + (pos++)] = base + j;
    }
    if (tid == 255) g_nv[b] = scnt[255];
}

// ---------------------------------------------------------------------------
// Kernel 3: pooled[b,i,:] = segsum(wt*x) / max(segsum(wt), 1e-6).
// All output stores are streaming (__stcs) so x stays resident in L2.
// Also writes new_mask row (folded k_newlen: max_counts recomputed per block,
// 16 L2-hit loads — cheap).
// ---------------------------------------------------------------------------
__global__ void k_pool(const float* __restrict__ x,
                       const int* __restrict__ seq_len,
                       float* __restrict__ out,
                       int write_mask) {
    int i   = blockIdx.x;
    int b   = blockIdx.y;
    int tid = threadIdx.x;                 // 128

    float4* orow = (float4*)(out + ((size_t)b * TT + i) * FF);
    int k = g_nv[b];
    int n = k + 1;

    if (i >= n) {
        __stcs(orow + tid, make_float4(0.f, 0.f, 0.f, 0.f));
    } else {
        int s = (i == 0) ? 0 : g_vlist[b * TT + i - 1];
        int e = (i < k) ? min(g_vlist[b * TT + i] + 2, TT) : TT;

        const float4* xb = (const float4*)(x + (size_t)b * TT * FF);
        const float*  wb = g_wt + b * TT;

        float4 acc0 = make_float4(0.f, 0.f, 0.f, 0.f);
        float4 acc1 = make_float4(0.f, 0.f, 0.f, 0.f);
        float  den0 = 0.f, den1 = 0.f;

        int t = s;
        for (; t + 1 < e; t += 2) {
            float  w0 = wb[t];
            float  w1 = wb[t + 1];
            float4 x0 = xb[(size_t)t * (FF / 4) + tid];
            float4 x1 = xb[(size_t)(t + 1) * (FF / 4) + tid];
            den0 += w0;  den1 += w1;
            acc0.x += w0 * x0.x;  acc0.y += w0 * x0.y;
            acc0.z += w0 * x0.z;  acc0.w += w0 * x0.w;
            acc1.x += w1 * x1.x;  acc1.y += w1 * x1.y;
            acc1.z += w1 * x1.z;  acc1.w += w1 * x1.w;
        }
        if (t < e) {
            float  w0 = wb[t];
            float4 x0 = xb[(size_t)t * (FF / 4) + tid];
            den0 += w0;
            acc0.x += w0 * x0.x;  acc0.y += w0 * x0.y;
            acc0.z += w0 * x0.z;  acc0.w += w0 * x0.w;
        }

        float den = fmaxf(den0 + den1, 1e-6f);
        float inv = 1.f / den;
        float4 r;
        r.x = (acc0.x + acc1.x) * inv;
        r.y = (acc0.y + acc1.y) * inv;
        r.z = (acc0.z + acc1.z) * inv;
        r.w = (acc0.w + acc1.w) * inv;
        __stcs(orow + tid, r);
    }

    if (write_mask && tid == 0) {
        // folded k_newlen: max over counts (16 cached loads)
        int mc = 0;
#pragma unroll
        for (int bb = 0; bb < BB; bb++) {
            int c = g_nv[bb] + 1;
            if (c > mc) mc = c;
        }
        int len  = min(seq_len[b], TT);
        int len0 = min(seq_len[0], TT);
        int nl   = (int)((float)len / (float)len0 * (float)mc);
        float* m = out + (size_t)BB * TT * FF;
        __stcs(&m[(size_t)b * TT + i], (i < nl) ? 1.f : 0.f);
    }
}

// ---------------------------------------------------------------------------
extern "C" void kernel_launch(void* const* d_in, const int* in_sizes, int n_in,
                              void* d_out, int out_size) {
    const float* x    = (const float*)d_in[0];   // [B,T,F] f32
    const float* w    = (const float*)d_in[1];   // [F,1]  f32
    const float* bias = (const float*)d_in[2];   // [1]    f32
    const int*   seq  = (const int*)d_in[3];     // [B]    i32
    float* out = (float*)d_out;

    int write_mask = (out_size >= BB * TT * FF + BB * TT) ? 1 : 0;

    k_gate<<<(BB * TT) / 8, 256>>>(x, w, bias);
    k_valleys<<<BB, 256>>>();
    dim3 grid(TT, BB);
    k_pool<<<grid, 128>>>(x, seq, out, write_mask);
}

// round 3
// speedup vs baseline: 1.2252x; 1.1533x over previous
#include <cuda_runtime.h>

#define BB 16
#define TT 2048
#define FF 512
#define SPB 4   // segments per k_pool block

// Scratch (allocation-free rule: device globals)
__device__ float g_wt[BB * TT];      // gate weights
__device__ int   g_vlist[BB * TT];   // packed valley positions per batch
__device__ int   g_nv[BB];           // number of valleys k per batch

// ---------------------------------------------------------------------------
// Kernel 1: wt = sigmoid(x·w + b). 2 rows per warp for doubled MLP.
// Default-cached loads warm L2 with all of x (64 MB < 126 MB L2).
// ---------------------------------------------------------------------------
__global__ void k_gate(const float* __restrict__ x,
                       const float* __restrict__ w,
                       const float* __restrict__ bias) {
    int warp = threadIdx.x >> 5;
    int lane = threadIdx.x & 31;
    int row0 = (blockIdx.x * 8 + warp) * 2;          // 16 rows / block
    if (row0 >= BB * TT) return;

    const float4* x0 = (const float4*)(x + (size_t)row0 * FF);
    const float4* x1 = x0 + FF / 4;
    const float4* wr = (const float4*)w;

    float s0 = 0.f, s1 = 0.f;
#pragma unroll
    for (int j = lane; j < FF / 4; j += 32) {
        float4 c = wr[j];
        float4 a = x0[j];
        float4 d = x1[j];
        s0 += a.x * c.x + a.y * c.y + a.z * c.z + a.w * c.w;
        s1 += d.x * c.x + d.y * c.y + d.z * c.z + d.w * c.w;
    }
#pragma unroll
    for (int o = 16; o; o >>= 1) {
        s0 += __shfl_down_sync(0xffffffffu, s0, o);
        s1 += __shfl_down_sync(0xffffffffu, s1, o);
    }
    if (lane == 0) {
        float bz = bias[0];
        g_wt[row0]     = 1.f / (1.f + expf(-(s0 + bz)));
        g_wt[row0 + 1] = 1.f / (1.f + expf(-(s1 + bz)));
    }
}

// ---------------------------------------------------------------------------
// Kernel 2: per batch, strict local minima of wt, left-packed positions.
// ---------------------------------------------------------------------------
__global__ void k_valleys() {
    __shared__ float sw[TT];
    __shared__ int   scnt[256];

    int b   = blockIdx.x;
    int tid = threadIdx.x;                 // 256 threads

    for (int t = tid; t < TT; t += 256) sw[t] = g_wt[b * TT + t];
    __syncthreads();

    const int PER = TT / 256;              // 8 consecutive t per thread
    int base = tid * PER;
    unsigned char fl[PER];
    int c = 0;
#pragma unroll
    for (int j = 0; j < PER; j++) {
        int   t   = base + j;
        float wtt = sw[t];
        float bef = (t == 0)      ? 0.f : sw[t - 1];
        float aft = (t == TT - 1) ? 0.f : sw[t + 1];
        bool  v   = (wtt < bef) && (wtt < aft);
        fl[j] = v ? 1 : 0;
        c += v ? 1 : 0;
    }
    scnt[tid] = c;
    __syncthreads();

    for (int off = 1; off < 256; off <<= 1) {
        int v = (tid >= off) ? scnt[tid - off] : 0;
        __syncthreads();
        scnt[tid] += v;
        __syncthreads();
    }

    int pos = scnt[tid] - c;               // exclusive prefix
#pragma unroll
    for (int j = 0; j < PER; j++) {
        if (fl[j]) g_vlist[b * TT + (pos++)] = base + j;
    }
    if (tid == 255) g_nv[b] = scnt[255];
}

// ---------------------------------------------------------------------------
// Kernel 3: streaming segment pooling. One block handles SPB consecutive
// segments of one batch, reading each x row exactly once; the 2-row overlap
// between consecutive segments is carried in registers (same ascending
// summation order as the reference => bitwise-stable). Segments >= counts
// stream zero rows. Streaming stores keep x resident in L2.
// ---------------------------------------------------------------------------
__global__ void k_pool(const float* __restrict__ x,
                       const int* __restrict__ seq_len,
                       float* __restrict__ out,
                       int write_mask) {
    int b   = blockIdx.y;
    int j   = blockIdx.x;
    int tid = threadIdx.x;                 // 128 threads, thread owns float4 col
    int k = g_nv[b];
    int n = k + 1;
    int i0 = j * SPB;

    // zero rows for padded segments in this block's range
    float4 z4 = make_float4(0.f, 0.f, 0.f, 0.f);
    for (int i = max(i0, n); i < i0 + SPB; i++)
        __stcs((float4*)(out + ((size_t)b * TT + i) * FF) + tid, z4);

    if (i0 < n) {
        int iEnd = min(i0 + SPB, n);
        const float4* xb = (const float4*)(x + (size_t)b * TT * FF);
        const float*  wb = g_wt + b * TT;
        const int*    vb = g_vlist + b * TT;

        float4 carry = z4;
        float  dcarry = 0.f;
        bool   have = false;

        for (int i = i0; i < iEnd; i++) {
            int S = (i == 0) ? 0 : vb[i - 1];
            int E = (i < k) ? min(vb[i] + 2, TT) : TT;

            float4 acc;
            float  den;
            int t;
            if (have) { acc = carry; den = dcarry; t = S + 2; }
            else      { acc = z4;    den = 0.f;    t = S;     }

            float4 c2 = z4;
            float  d2 = 0.f;
            int ov = E - 2;                        // overlap rows: [E-2, E)
            for (; t < E; t++) {
                float  wv = wb[t];
                float4 xv = xb[(size_t)t * (FF / 4) + tid];
                acc.x += wv * xv.x;  acc.y += wv * xv.y;
                acc.z += wv * xv.z;  acc.w += wv * xv.w;
                den += wv;
                if (t >= ov) {
                    c2.x += wv * xv.x;  c2.y += wv * xv.y;
                    c2.z += wv * xv.z;  c2.w += wv * xv.w;
                    d2 += wv;
                }
            }
            carry = c2; dcarry = d2; have = true;

            float inv = 1.f / fmaxf(den, 1e-6f);
            float4 r;
            r.x = acc.x * inv;  r.y = acc.y * inv;
            r.z = acc.z * inv;  r.w = acc.w * inv;
            __stcs((float4*)(out + ((size_t)b * TT + i) * FF) + tid, r);
        }
    }

    if (write_mask && tid < SPB) {
        int i = i0 + tid;
        int mc = 0;
#pragma unroll
        for (int bb = 0; bb < BB; bb++) {
            int c = g_nv[bb] + 1;
            if (c > mc) mc = c;
        }
        int len  = min(seq_len[b], TT);
        int len0 = min(seq_len[0], TT);
        int nl   = (int)((float)len / (float)len0 * (float)mc);
        float* m = out + (size_t)BB * TT * FF;
        __stcs(&m[(size_t)b * TT + i], (i < nl) ? 1.f : 0.f);
    }
}

// ---------------------------------------------------------------------------
extern "C" void kernel_launch(void* const* d_in, const int* in_sizes, int n_in,
                              void* d_out, int out_size) {
    const float* x    = (const float*)d_in[0];   // [B,T,F] f32
    const float* w    = (const float*)d_in[1];   // [F,1]  f32
    const float* bias = (const float*)d_in[2];   // [1]    f32
    const int*   seq  = (const int*)d_in[3];     // [B]    i32
    float* out = (float*)d_out;

    int write_mask = (out_size >= BB * TT * FF + BB * TT) ? 1 : 0;

    k_gate<<<(BB * TT) / 16, 256>>>(x, w, bias);
    k_valleys<<<BB, 256>>>();
    dim3 grid(TT / SPB, BB);
    k_pool<<<grid, 128>>>(x, seq, out, write_mask);
}